// round 12
// baseline (speedup 1.0000x reference)
#include <cuda_runtime.h>
#include <math.h>
#include <stdint.h>

#define H 4096
#define NEXP 64
#define TOPK 8
#define TILE_M 64
#define KC 64
#define NCHUNK (H / KC)          // 64
#define SA 68                    // smem row stride words (68 % 32 == 4 -> conflict-free frags)

#define A_BUF_W (TILE_M * SA)               // 4352 words
#define B_BUF_W (NEXP * SA)                 // 4352 words
#define B_BASE_W (2 * A_BUF_W)              // 8704
#define SMEM_W  (B_BASE_W + 2 * B_BUF_W)    // 17408 words = 69632 B
#define LOGIT_STRIDE 65

// device scratch (alloc-free rule)
__device__ int   g_icounts[NEXP];
__device__ int   g_fix_count;
__device__ int   g_fix_list[16384];
__device__ float g_thresh;       // gap threshold chosen by precision probe

static __device__ __forceinline__ void mma_tf32(float* d, const uint32_t* a, const uint32_t* b) {
    asm volatile(
        "mma.sync.aligned.m16n8k8.row.col.f32.tf32.tf32.f32 "
        "{%0,%1,%2,%3}, {%4,%5,%6,%7}, {%8,%9}, {%0,%1,%2,%3};"
        : "+f"(d[0]), "+f"(d[1]), "+f"(d[2]), "+f"(d[3])
        : "r"(a[0]), "r"(a[1]), "r"(a[2]), "r"(a[3]), "r"(b[0]), "r"(b[1]));
}

// ---------------------------------------------------------------------------
// Precision probe: does the tf32 mma path truncate fp32 operands?
// A = 1 + 2^-20 everywhere, B = 1 -> D = 8*(1+2^-20) if full precision kept,
// exactly 8.0 if operands truncated to tf32. Sets the fixup gap threshold.
// Also zeroes the expert counters.
// ---------------------------------------------------------------------------
__global__ void probe_kernel() {
    if (threadIdx.x < NEXP) g_icounts[threadIdx.x] = 0;
    float d[4] = {0.f, 0.f, 0.f, 0.f};
    uint32_t a[4], b[2];
    const float av = 1.0f + 9.5367431640625e-7f;   // 1 + 2^-20
    a[0] = a[1] = a[2] = a[3] = __float_as_uint(av);
    b[0] = b[1] = __float_as_uint(1.0f);
    mma_tf32(d, a, b);
    if (threadIdx.x == 0)
        g_thresh = (d[0] == 8.0f) ? 3e-3f : 1e-4f;
}

// ---------------------------------------------------------------------------
// 1-pass GEMM via mma.sync tf32 (raw fp32 bits, no cvt) + fused top-8
// epilogue with counting. CTA = 64 tokens x 64 experts, 8 warps
// (mw = wid&1: 32 tokens, nw = wid>>1: 16 experts), KC=64 double-buffered.
// ---------------------------------------------------------------------------
__global__ __launch_bounds__(256, 2) void gate_mma(
    const float* __restrict__ x, const float* __restrict__ W,
    float* __restrict__ out, int Ntok)
{
    extern __shared__ float sm[];
    __shared__ int scnt[NEXP];

    const int t    = threadIdx.x;
    const int wid  = t >> 5;
    const int lane = t & 31;
    const int gid  = lane >> 2;
    const int tig  = lane & 3;
    const int mw   = wid & 1;        // 32 tokens
    const int nw   = wid >> 1;       // 16 experts
    const int tok0 = blockIdx.x * TILE_M;

    if (t < NEXP) scnt[t] = 0;

    float d[2][2][4];
#pragma unroll
    for (int i = 0; i < 2; i++)
#pragma unroll
        for (int j = 0; j < 2; j++)
#pragma unroll
            for (int k = 0; k < 4; k++) d[i][j][k] = 0.f;

    const float* xb = x + (size_t)tok0 * H;

    float4 ra[4], rb[4];

    // ---- prologue: chunk 0 into stage 0 ----
#pragma unroll
    for (int i = 0; i < 4; i++) {
        int f = t + 256 * i;                  // 0..1023 float4
        int row = f >> 4, c4 = f & 15;
        ra[i] = *(const float4*)(xb + (size_t)row * H + c4 * 4);
        rb[i] = *(const float4*)(W + (size_t)row * H + c4 * 4);
    }
#pragma unroll
    for (int i = 0; i < 4; i++) {
        int f = t + 256 * i;
        int row = f >> 4, c4 = f & 15;
        *(float4*)(sm + 0 * A_BUF_W + row * SA + c4 * 4) = ra[i];
        *(float4*)(sm + B_BASE_W + 0 * B_BUF_W + row * SA + c4 * 4) = rb[i];
    }
    __syncthreads();

    // ---- main loop ----
    for (int c = 0; c < NCHUNK; c++) {
        const int s = c & 1;
        const bool more = (c + 1 < NCHUNK);

        if (more) {
            const float* xc = xb + (size_t)(c + 1) * KC;
            const float* wc = W + (size_t)(c + 1) * KC;
#pragma unroll
            for (int i = 0; i < 4; i++) {
                int f = t + 256 * i;
                int row = f >> 4, c4 = f & 15;
                ra[i] = *(const float4*)(xc + (size_t)row * H + c4 * 4);
                rb[i] = *(const float4*)(wc + (size_t)row * H + c4 * 4);
            }
        }

        const float* A = sm + s * A_BUF_W;
        const float* B = sm + B_BASE_W + s * B_BUF_W;

#pragma unroll
        for (int slab = 0; slab < 8; slab++) {
            const int k0 = slab * 8;
            uint32_t af[2][4], bf[2][2];
#pragma unroll
            for (int mt = 0; mt < 2; mt++) {
                int r = mw * 32 + mt * 16 + gid;
                af[mt][0] = __float_as_uint(A[(r    ) * SA + k0 + tig    ]);
                af[mt][1] = __float_as_uint(A[(r + 8) * SA + k0 + tig    ]);
                af[mt][2] = __float_as_uint(A[(r    ) * SA + k0 + tig + 4]);
                af[mt][3] = __float_as_uint(A[(r + 8) * SA + k0 + tig + 4]);
            }
#pragma unroll
            for (int nt = 0; nt < 2; nt++) {
                int e = nw * 16 + nt * 8 + gid;
                bf[nt][0] = __float_as_uint(B[e * SA + k0 + tig    ]);
                bf[nt][1] = __float_as_uint(B[e * SA + k0 + tig + 4]);
            }
#pragma unroll
            for (int mt = 0; mt < 2; mt++)
#pragma unroll
                for (int nt = 0; nt < 2; nt++)
                    mma_tf32(d[mt][nt], af[mt], bf[nt]);
        }

        if (more) {
            const int st = s ^ 1;
#pragma unroll
            for (int i = 0; i < 4; i++) {
                int f = t + 256 * i;
                int row = f >> 4, c4 = f & 15;
                *(float4*)(sm + st * A_BUF_W + row * SA + c4 * 4) = ra[i];
                *(float4*)(sm + B_BASE_W + st * B_BUF_W + row * SA + c4 * 4) = rb[i];
            }
        }
        __syncthreads();
    }

    // ---- D fragments -> smem logits [64][65] ----
#pragma unroll
    for (int mt = 0; mt < 2; mt++)
#pragma unroll
        for (int nt = 0; nt < 2; nt++) {
            int r = mw * 32 + mt * 16 + gid;
            int cc = nw * 16 + nt * 8 + 2 * tig;
            sm[(r    ) * LOGIT_STRIDE + cc    ] = d[mt][nt][0];
            sm[(r    ) * LOGIT_STRIDE + cc + 1] = d[mt][nt][1];
            sm[(r + 8) * LOGIT_STRIDE + cc    ] = d[mt][nt][2];
            sm[(r + 8) * LOGIT_STRIDE + cc + 1] = d[mt][nt][3];
        }
    __syncthreads();

    // ---- epilogue: top-10 scan + softmax + gap flag + counting ----
    if (t < TILE_M) {
        const float* row = sm + t * LOGIT_STRIDE;
        float sv[10]; int si[10];
        unsigned long long used = 0ull;
#pragma unroll 1
        for (int j = 0; j < 10; j++) {
            float best = -3.4e38f; int bi = 0;
#pragma unroll
            for (int e = 0; e < NEXP; e++) {
                float v = row[e];
                if (!((used >> e) & 1ull) && v > best) { best = v; bi = e; }
            }
            used |= 1ull << bi;
            sv[j] = best; si[j] = bi;
        }
        float ming = 3.4e38f;
#pragma unroll
        for (int j = 0; j < 9; j++) ming = fminf(ming, sv[j] - sv[j + 1]);

        const int g = tok0 + t;
        if (ming < g_thresh) {
            int pos = atomicAdd(&g_fix_count, 1);
            g_fix_list[pos] = g;
        }
        float m = sv[0], ex[TOPK], ssum = 0.f;
#pragma unroll
        for (int j = 0; j < TOPK; j++) { ex[j] = expf(sv[j] - m); ssum += ex[j]; }
        float inv = 1.f / ssum;
        float* score_out = out + (size_t)g * TOPK;
        float* idx_out   = out + (size_t)Ntok * TOPK + (size_t)g * TOPK;
#pragma unroll
        for (int j = 0; j < TOPK; j++) {
            score_out[j] = ex[j] * inv;
            idx_out[j]   = (float)si[j];
            atomicAdd(&scnt[si[j]], 1);
        }
    }
    __syncthreads();
    if (t < NEXP && scnt[t]) atomicAdd(&g_icounts[t], scnt[t]);
}

// ---------------------------------------------------------------------------
// Exact fixup: compensated fp32 recompute for flagged tokens, top-8 in
// double, overwrite outputs, patch expert counts.
// ---------------------------------------------------------------------------
__global__ __launch_bounds__(256) void fixup_kernel(
    const float* __restrict__ x, const float* __restrict__ W,
    float* __restrict__ out, int Ntok)
{
    const int t = threadIdx.x;
    const int e = t >> 2;
    const int sub = t & 3;
    const int nfix = g_fix_count;

    __shared__ double lg[NEXP];

    for (int fi = blockIdx.x; fi < nfix; fi += gridDim.x) {
        const int tok = g_fix_list[fi];
        const float* xr = x + (size_t)tok * H;
        const float* wr = W + (size_t)e * H;

        float s = 0.f, c = 0.f;
        const int kb = sub * (H / 4);
#pragma unroll 4
        for (int k = kb; k < kb + H / 4; k++) {
            float xv = xr[k], wv = wr[k];
            float p  = xv * wv;
            float pe = fmaf(xv, wv, -p);
            float tt = s + p;
            c += (fabsf(s) >= fabsf(p)) ? ((s - tt) + p) : ((p - tt) + s);
            s  = tt;
            c += pe;
        }
        double dd = (double)s + (double)c;
        dd += __shfl_down_sync(0xffffffffu, dd, 1);
        dd += __shfl_down_sync(0xffffffffu, dd, 2);
        if (sub == 0) lg[e] = dd;
        __syncthreads();

        if (t == 0) {
            float* score_out = out + (size_t)tok * TOPK;
            float* idx_out   = out + (size_t)Ntok * TOPK + (size_t)tok * TOPK;
            int olde[TOPK];
#pragma unroll
            for (int j = 0; j < TOPK; j++) olde[j] = (int)idx_out[j];

            double sv[TOPK]; int si[TOPK];
#pragma unroll 1
            for (int j = 0; j < TOPK; j++) {
                double best = -1e300; int bi = 0;
                for (int ee = 0; ee < NEXP; ee++) {
                    double v = lg[ee];
                    if (v > best) { best = v; bi = ee; }
                }
                sv[j] = best; si[j] = bi;
                lg[bi] = -1e300;
            }
            float m = (float)sv[0], ex[TOPK], ssum = 0.f;
#pragma unroll
            for (int j = 0; j < TOPK; j++) { ex[j] = expf((float)sv[j] - m); ssum += ex[j]; }
            float inv = 1.f / ssum;
#pragma unroll
            for (int j = 0; j < TOPK; j++) {
                score_out[j] = ex[j] * inv;
                idx_out[j]   = (float)si[j];
                if (si[j] != olde[j]) {
                    atomicAdd(&g_icounts[si[j]], 1);
                    atomicSub(&g_icounts[olde[j]], 1);
                }
            }
        }
        __syncthreads();
    }
}

// ---------------------------------------------------------------------------
// loss = 0.01 * sum_e (count_e/N - 1/64)^2; resets fixup counter.
// ---------------------------------------------------------------------------
__global__ void loss_kernel(float* __restrict__ out, int Ntok)
{
    const int t = threadIdx.x;   // 64
    float dd = (float)g_icounts[t] / (float)Ntok - (1.0f / 64.0f);
    float v = dd * dd;
#pragma unroll
    for (int off = 16; off > 0; off >>= 1)
        v += __shfl_down_sync(0xffffffffu, v, off);
    __shared__ float red[2];
    if ((t & 31) == 0) red[t >> 5] = v;
    __syncthreads();
    if (t == 0) {
        out[0] = 0.01f * (red[0] + red[1]);
        g_fix_count = 0;    // reset for next graph replay
    }
}

extern "C" void kernel_launch(void* const* d_in, const int* in_sizes, int n_in,
                              void* d_out, int out_size)
{
    const float* x = (const float*)d_in[0];
    const float* W = (const float*)d_in[1];
    float* out = (float*)d_out;

    int Ntok  = in_sizes[0] / H;     // 16384
    int n_sel = Ntok * TOPK;         // 131072

    cudaFuncSetAttribute(gate_mma, cudaFuncAttributeMaxDynamicSharedMemorySize, SMEM_W * 4);

    probe_kernel<<<1, 64>>>();
    gate_mma<<<Ntok / TILE_M, 256, SMEM_W * 4>>>(x, W, out, Ntok);
    fixup_kernel<<<128, 256>>>(x, W, out, Ntok);
    loss_kernel<<<1, 64>>>(out + (size_t)2 * n_sel, Ntok);
}

// round 14
// speedup vs baseline: 11.3343x; 11.3343x over previous
#include <cuda_runtime.h>
#include <math.h>
#include <stdint.h>

#define H 4096
#define NEXP 64
#define TOPK 8
#define TILE_M 64
#define KC 64
#define NCHUNK (H / KC)          // 64
#define SA 68                    // gate smem row stride words

#define A_BUF_W (TILE_M * SA)
#define B_BUF_W (NEXP * SA)
#define B_BASE_W (2 * A_BUF_W)
#define SMEM_W  (B_BASE_W + 2 * B_BUF_W)    // 17408 words = 69632 B
#define LOGIT_STRIDE 65
#define GATE_THRESH 3e-3f
#define REFINE_THRESH 1e-4f

// device scratch (alloc-free rule)
__device__ int g_icounts[NEXP];
__device__ int g_fix_count;
__device__ int g_fix_list[16384];
__device__ int g_fix2_count;
__device__ int g_fix2_list[16384];

static __device__ __forceinline__ uint32_t cvt_tf32(float f) {
    uint32_t r;
    asm("cvt.rna.tf32.f32 %0, %1;" : "=r"(r) : "f"(f));
    return r;
}
static __device__ __forceinline__ void mma_tf32(float* d, const uint32_t* a, const uint32_t* b) {
    asm volatile(
        "mma.sync.aligned.m16n8k8.row.col.f32.tf32.tf32.f32 "
        "{%0,%1,%2,%3}, {%4,%5,%6,%7}, {%8,%9}, {%0,%1,%2,%3};"
        : "+f"(d[0]), "+f"(d[1]), "+f"(d[2]), "+f"(d[3])
        : "r"(a[0]), "r"(a[1]), "r"(a[2]), "r"(a[3]), "r"(b[0]), "r"(b[1]));
}

// ---------------------------------------------------------------------------
// 1-pass tf32 GEMM (rna-rounded operands) + fused top-8 epilogue + counting.
// CTA = 64 tokens x 64 experts, 8 warps, KC=64 double-buffered, 2 CTAs/SM.
// ---------------------------------------------------------------------------
__global__ __launch_bounds__(256, 2) void gate_mma(
    const float* __restrict__ x, const float* __restrict__ W,
    float* __restrict__ out, int Ntok)
{
    extern __shared__ float sm[];
    __shared__ int scnt[NEXP];

    const int t    = threadIdx.x;
    const int wid  = t >> 5;
    const int lane = t & 31;
    const int gid  = lane >> 2;
    const int tig  = lane & 3;
    const int mw   = wid & 1;
    const int nw   = wid >> 1;
    const int tok0 = blockIdx.x * TILE_M;

    if (t < NEXP) scnt[t] = 0;

    float d[2][2][4];
#pragma unroll
    for (int i = 0; i < 2; i++)
#pragma unroll
        for (int j = 0; j < 2; j++)
#pragma unroll
            for (int k = 0; k < 4; k++) d[i][j][k] = 0.f;

    const float* xb = x + (size_t)tok0 * H;
    float4 ra[4], rb[4];

#pragma unroll
    for (int i = 0; i < 4; i++) {
        int f = t + 256 * i;
        int row = f >> 4, c4 = f & 15;
        ra[i] = *(const float4*)(xb + (size_t)row * H + c4 * 4);
        rb[i] = *(const float4*)(W + (size_t)row * H + c4 * 4);
    }
#pragma unroll
    for (int i = 0; i < 4; i++) {
        int f = t + 256 * i;
        int row = f >> 4, c4 = f & 15;
        uint4 av, bv;
        av.x = cvt_tf32(ra[i].x); av.y = cvt_tf32(ra[i].y);
        av.z = cvt_tf32(ra[i].z); av.w = cvt_tf32(ra[i].w);
        bv.x = cvt_tf32(rb[i].x); bv.y = cvt_tf32(rb[i].y);
        bv.z = cvt_tf32(rb[i].z); bv.w = cvt_tf32(rb[i].w);
        *(uint4*)(sm + 0 * A_BUF_W + row * SA + c4 * 4) = av;
        *(uint4*)(sm + B_BASE_W + 0 * B_BUF_W + row * SA + c4 * 4) = bv;
    }
    __syncthreads();

    for (int c = 0; c < NCHUNK; c++) {
        const int s = c & 1;
        const bool more = (c + 1 < NCHUNK);

        if (more) {
            const float* xc = xb + (size_t)(c + 1) * KC;
            const float* wc = W + (size_t)(c + 1) * KC;
#pragma unroll
            for (int i = 0; i < 4; i++) {
                int f = t + 256 * i;
                int row = f >> 4, c4 = f & 15;
                ra[i] = *(const float4*)(xc + (size_t)row * H + c4 * 4);
                rb[i] = *(const float4*)(wc + (size_t)row * H + c4 * 4);
            }
        }

        const float* A = sm + s * A_BUF_W;
        const float* B = sm + B_BASE_W + s * B_BUF_W;

#pragma unroll
        for (int slab = 0; slab < 8; slab++) {
            const int k0 = slab * 8;
            uint32_t af[2][4], bf[2][2];
#pragma unroll
            for (int mt = 0; mt < 2; mt++) {
                int r = mw * 32 + mt * 16 + gid;
                af[mt][0] = __float_as_uint(A[(r    ) * SA + k0 + tig    ]);
                af[mt][1] = __float_as_uint(A[(r + 8) * SA + k0 + tig    ]);
                af[mt][2] = __float_as_uint(A[(r    ) * SA + k0 + tig + 4]);
                af[mt][3] = __float_as_uint(A[(r + 8) * SA + k0 + tig + 4]);
            }
#pragma unroll
            for (int nt = 0; nt < 2; nt++) {
                int e = nw * 16 + nt * 8 + gid;
                bf[nt][0] = __float_as_uint(B[e * SA + k0 + tig    ]);
                bf[nt][1] = __float_as_uint(B[e * SA + k0 + tig + 4]);
            }
#pragma unroll
            for (int mt = 0; mt < 2; mt++)
#pragma unroll
                for (int nt = 0; nt < 2; nt++)
                    mma_tf32(d[mt][nt], af[mt], bf[nt]);
        }

        if (more) {
            const int st = s ^ 1;
#pragma unroll
            for (int i = 0; i < 4; i++) {
                int f = t + 256 * i;
                int row = f >> 4, c4 = f & 15;
                uint4 av, bv;
                av.x = cvt_tf32(ra[i].x); av.y = cvt_tf32(ra[i].y);
                av.z = cvt_tf32(ra[i].z); av.w = cvt_tf32(ra[i].w);
                bv.x = cvt_tf32(rb[i].x); bv.y = cvt_tf32(rb[i].y);
                bv.z = cvt_tf32(rb[i].z); bv.w = cvt_tf32(rb[i].w);
                *(uint4*)(sm + st * A_BUF_W + row * SA + c4 * 4) = av;
                *(uint4*)(sm + B_BASE_W + st * B_BUF_W + row * SA + c4 * 4) = bv;
            }
        }
        __syncthreads();
    }

    // D fragments -> smem logits [64][65]
#pragma unroll
    for (int mt = 0; mt < 2; mt++)
#pragma unroll
        for (int nt = 0; nt < 2; nt++) {
            int r = mw * 32 + mt * 16 + gid;
            int cc = nw * 16 + nt * 8 + 2 * tig;
            sm[(r    ) * LOGIT_STRIDE + cc    ] = d[mt][nt][0];
            sm[(r    ) * LOGIT_STRIDE + cc + 1] = d[mt][nt][1];
            sm[(r + 8) * LOGIT_STRIDE + cc    ] = d[mt][nt][2];
            sm[(r + 8) * LOGIT_STRIDE + cc + 1] = d[mt][nt][3];
        }
    __syncthreads();

    if (t < TILE_M) {
        const float* row = sm + t * LOGIT_STRIDE;
        float sv[10]; int si[10];
        unsigned long long used = 0ull;
#pragma unroll 1
        for (int j = 0; j < 10; j++) {
            float best = -3.4e38f; int bi = 0;
#pragma unroll
            for (int e = 0; e < NEXP; e++) {
                float v = row[e];
                if (!((used >> e) & 1ull) && v > best) { best = v; bi = e; }
            }
            used |= 1ull << bi;
            sv[j] = best; si[j] = bi;
        }
        float ming = 3.4e38f;
#pragma unroll
        for (int j = 0; j < 9; j++) ming = fminf(ming, sv[j] - sv[j + 1]);

        const int g = tok0 + t;
        if (ming < GATE_THRESH) {
            int pos = atomicAdd(&g_fix_count, 1);
            g_fix_list[pos] = g;
        }
        float m = sv[0], ex[TOPK], ssum = 0.f;
#pragma unroll
        for (int j = 0; j < TOPK; j++) { ex[j] = expf(sv[j] - m); ssum += ex[j]; }
        float inv = 1.f / ssum;
        float* score_out = out + (size_t)g * TOPK;
        float* idx_out   = out + (size_t)Ntok * TOPK + (size_t)g * TOPK;
#pragma unroll
        for (int j = 0; j < TOPK; j++) {
            score_out[j] = ex[j] * inv;
            idx_out[j]   = (float)si[j];
            atomicAdd(&scnt[si[j]], 1);
        }
    }
    __syncthreads();
    if (t < NEXP && scnt[t]) atomicAdd(&g_icounts[t], scnt[t]);
}

// ---------------------------------------------------------------------------
// Tier-1 refine: plain fp32 recompute (coalesced, smem-tiled W), 8 tokens
// per block, warp-per-token, 2 experts per lane. Re-ranks with 1e-4 gap
// threshold; ambiguous -> tier-2 list; else overwrite outputs + patch counts.
// ---------------------------------------------------------------------------
__global__ __launch_bounds__(256, 2) void refine_kernel(
    const float* __restrict__ x, const float* __restrict__ W,
    float* __restrict__ out, int Ntok)
{
    __shared__ float Wc[NEXP * 133];
    __shared__ float xc[8 * 133];
    __shared__ float lgs[8][66];
    __shared__ int   toks[8];

    const int t    = threadIdx.x;
    const int wid  = t >> 5;
    const int lane = t & 31;
    const int nfix = g_fix_count;

    for (int base = blockIdx.x * 8; base < nfix; base += gridDim.x * 8) {
        const int nt = min(8, nfix - base);
        if (t < 8) toks[t] = g_fix_list[base + ((t < nt) ? t : 0)];
        __syncthreads();

        float acc0 = 0.f, acc1 = 0.f;
        for (int ch = 0; ch < 32; ch++) {
            // stage W chunk [64][128] coalesced
#pragma unroll
            for (int i = 0; i < 8; i++) {
                int f = t + 256 * i;              // 0..2047 f4
                int row = f >> 5, kq = f & 31;
                float4 v = *(const float4*)(W + (size_t)row * H + ch * 128 + kq * 4);
                float* dst = Wc + row * 133 + kq * 4;
                dst[0] = v.x; dst[1] = v.y; dst[2] = v.z; dst[3] = v.w;
            }
            // stage x chunks for 8 tokens
            {
                int row = t >> 5, kq = t & 31;
                float4 v = *(const float4*)(x + (size_t)toks[row] * H + ch * 128 + kq * 4);
                float* dst = xc + row * 133 + kq * 4;
                dst[0] = v.x; dst[1] = v.y; dst[2] = v.z; dst[3] = v.w;
            }
            __syncthreads();

            const float* xr = xc + wid * 133;
            const float* w0 = Wc + lane * 133;
            const float* w1 = Wc + (lane + 32) * 133;
#pragma unroll 16
            for (int k = 0; k < 128; k++) {
                float xv = xr[k];
                acc0 = fmaf(w0[k], xv, acc0);
                acc1 = fmaf(w1[k], xv, acc1);
            }
            __syncthreads();
        }
        lgs[wid][lane]      = acc0;
        lgs[wid][lane + 32] = acc1;
        __syncthreads();

        if (t < nt) {
            const int tok = toks[t];
            const float* row = lgs[t];
            float sv[10]; int si[10];
            unsigned long long used = 0ull;
#pragma unroll 1
            for (int j = 0; j < 10; j++) {
                float best = -3.4e38f; int bi = 0;
#pragma unroll
                for (int e = 0; e < NEXP; e++) {
                    float v = row[e];
                    if (!((used >> e) & 1ull) && v > best) { best = v; bi = e; }
                }
                used |= 1ull << bi;
                sv[j] = best; si[j] = bi;
            }
            float ming = 3.4e38f;
#pragma unroll
            for (int j = 0; j < 9; j++) ming = fminf(ming, sv[j] - sv[j + 1]);

            if (ming < REFINE_THRESH) {
                int pos = atomicAdd(&g_fix2_count, 1);
                g_fix2_list[pos] = tok;
            } else {
                float* score_out = out + (size_t)tok * TOPK;
                float* idx_out   = out + (size_t)Ntok * TOPK + (size_t)tok * TOPK;
                float m = sv[0], ex[TOPK], ssum = 0.f;
#pragma unroll
                for (int j = 0; j < TOPK; j++) { ex[j] = expf(sv[j] - m); ssum += ex[j]; }
                float inv = 1.f / ssum;
#pragma unroll
                for (int j = 0; j < TOPK; j++) {
                    int olde = (int)idx_out[j];
                    score_out[j] = ex[j] * inv;
                    idx_out[j]   = (float)si[j];
                    if (si[j] != olde) {
                        atomicAdd(&g_icounts[si[j]], 1);
                        atomicSub(&g_icounts[olde], 1);
                    }
                }
            }
        }
        __syncthreads();
    }
}

// ---------------------------------------------------------------------------
// Tier-2 exact: compensated (TwoProd+Neumaier) recompute, smem-tiled and
// coalesced, 1 token per block. Double re-rank, overwrite, patch counts.
// ---------------------------------------------------------------------------
__global__ __launch_bounds__(256, 2) void exact_kernel(
    const float* __restrict__ x, const float* __restrict__ W,
    float* __restrict__ out, int Ntok)
{
    __shared__ float  Wc[NEXP * 133];
    __shared__ float  xcc[132];
    __shared__ double lg[NEXP];

    const int t   = threadIdx.x;
    const int e   = t >> 2;
    const int sub = t & 3;
    const int nfix2 = g_fix2_count;

    for (int fi = blockIdx.x; fi < nfix2; fi += gridDim.x) {
        const int tok = g_fix2_list[fi];
        float s = 0.f, c = 0.f;

        for (int ch = 0; ch < 32; ch++) {
#pragma unroll
            for (int i = 0; i < 8; i++) {
                int f = t + 256 * i;
                int row = f >> 5, kq = f & 31;
                float4 v = *(const float4*)(W + (size_t)row * H + ch * 128 + kq * 4);
                float* dst = Wc + row * 133 + kq * 4;
                dst[0] = v.x; dst[1] = v.y; dst[2] = v.z; dst[3] = v.w;
            }
            if (t < 32) {
                float4 v = *(const float4*)(x + (size_t)tok * H + ch * 128 + t * 4);
                xcc[t * 4 + 0] = v.x; xcc[t * 4 + 1] = v.y;
                xcc[t * 4 + 2] = v.z; xcc[t * 4 + 3] = v.w;
            }
            __syncthreads();

            const float* wr = Wc + e * 133;
#pragma unroll 8
            for (int j = 0; j < 32; j++) {
                int k = sub + 4 * j;
                float xv = xcc[k], wv = wr[k];
                float p  = xv * wv;
                float pe = fmaf(xv, wv, -p);
                float tt = s + p;
                c += (fabsf(s) >= fabsf(p)) ? ((s - tt) + p) : ((p - tt) + s);
                s  = tt;
                c += pe;
            }
            __syncthreads();
        }
        double dd = (double)s + (double)c;
        dd += __shfl_down_sync(0xffffffffu, dd, 1);
        dd += __shfl_down_sync(0xffffffffu, dd, 2);
        if (sub == 0) lg[e] = dd;
        __syncthreads();

        if (t == 0) {
            float* score_out = out + (size_t)tok * TOPK;
            float* idx_out   = out + (size_t)Ntok * TOPK + (size_t)tok * TOPK;
            int olde[TOPK];
#pragma unroll
            for (int j = 0; j < TOPK; j++) olde[j] = (int)idx_out[j];

            double sv[TOPK]; int si[TOPK];
#pragma unroll 1
            for (int j = 0; j < TOPK; j++) {
                double best = -1e300; int bi = 0;
                for (int ee = 0; ee < NEXP; ee++) {
                    double v = lg[ee];
                    if (v > best) { best = v; bi = ee; }
                }
                sv[j] = best; si[j] = bi;
                lg[bi] = -1e300;
            }
            float m = (float)sv[0], ex[TOPK], ssum = 0.f;
#pragma unroll
            for (int j = 0; j < TOPK; j++) { ex[j] = expf((float)sv[j] - m); ssum += ex[j]; }
            float inv = 1.f / ssum;
#pragma unroll
            for (int j = 0; j < TOPK; j++) {
                score_out[j] = ex[j] * inv;
                idx_out[j]   = (float)si[j];
                if (si[j] != olde[j]) {
                    atomicAdd(&g_icounts[si[j]], 1);
                    atomicSub(&g_icounts[olde[j]], 1);
                }
            }
        }
        __syncthreads();
    }
}

// ---------------------------------------------------------------------------
// loss = 0.01 * sum_e (count_e/N - 1/64)^2; resets all state for replay.
// ---------------------------------------------------------------------------
__global__ void loss_kernel(float* __restrict__ out, int Ntok)
{
    const int t = threadIdx.x;   // 64
    float dd = (float)g_icounts[t] / (float)Ntok - (1.0f / 64.0f);
    float v = dd * dd;
#pragma unroll
    for (int off = 16; off > 0; off >>= 1)
        v += __shfl_down_sync(0xffffffffu, v, off);
    __shared__ float red[2];
    if ((t & 31) == 0) red[t >> 5] = v;
    __syncthreads();
    g_icounts[t] = 0;
    if (t == 0) {
        out[0] = 0.01f * (red[0] + red[1]);
        g_fix_count  = 0;
        g_fix2_count = 0;
    }
}

extern "C" void kernel_launch(void* const* d_in, const int* in_sizes, int n_in,
                              void* d_out, int out_size)
{
    const float* x = (const float*)d_in[0];
    const float* W = (const float*)d_in[1];
    float* out = (float*)d_out;

    int Ntok  = in_sizes[0] / H;     // 16384
    int n_sel = Ntok * TOPK;         // 131072

    cudaFuncSetAttribute(gate_mma, cudaFuncAttributeMaxDynamicSharedMemorySize, SMEM_W * 4);

    gate_mma<<<Ntok / TILE_M, 256, SMEM_W * 4>>>(x, W, out, Ntok);
    refine_kernel<<<592, 256>>>(x, W, out, Ntok);
    exact_kernel<<<256, 256>>>(x, W, out, Ntok);
    loss_kernel<<<1, 64>>>(out + (size_t)2 * n_sel, Ntok);
}

// round 16
// speedup vs baseline: 12.4317x; 1.0968x over previous
#include <cuda_runtime.h>
#include <math.h>
#include <stdint.h>

#define H 4096
#define NEXP 64
#define TOPK 8
#define TILE_M 64
#define KC 64
#define NCHUNK (H / KC)          // 64
#define NST 3
#define SA 68                    // smem row stride words (68%32==4 -> conflict-free frags)

#define A_BUF_W (TILE_M * SA)               // 4352 words
#define B_BUF_W (NEXP * SA)                 // 4352 words
#define STG_W   (A_BUF_W + B_BUF_W)         // 8704 words
#define SMEM_BYTES (NST * STG_W * 4)        // 104448 B
#define LOGIT_STRIDE 65
#define GATE_THRESH 3e-3f
#define REFINE_THRESH 1e-4f

// device scratch (alloc-free rule)
__device__ int g_icounts[NEXP];
__device__ int g_fix_count;
__device__ int g_fix_list[16384];
__device__ int g_fix2_count;
__device__ int g_fix2_list[16384];

static __device__ __forceinline__ uint32_t s2u(const void* p) {
    uint32_t a;
    asm("{ .reg .u64 t; cvta.to.shared.u64 t, %1; cvt.u32.u64 %0, t; }" : "=r"(a) : "l"(p));
    return a;
}
#define CP_ASYNC(dst, src) \
    asm volatile("cp.async.cg.shared.global [%0], [%1], 16;" :: "r"(dst), "l"(src))
#define CP_COMMIT() asm volatile("cp.async.commit_group;" ::: "memory")
#define CP_WAIT2()  asm volatile("cp.async.wait_group 2;" ::: "memory")

static __device__ __forceinline__ void mma_tf32(float* d, const uint32_t* a, const uint32_t* b) {
    asm volatile(
        "mma.sync.aligned.m16n8k8.row.col.f32.tf32.tf32.f32 "
        "{%0,%1,%2,%3}, {%4,%5,%6,%7}, {%8,%9}, {%0,%1,%2,%3};"
        : "+f"(d[0]), "+f"(d[1]), "+f"(d[2]), "+f"(d[3])
        : "r"(a[0]), "r"(a[1]), "r"(a[2]), "r"(a[3]), "r"(b[0]), "r"(b[1]));
}

// ---------------------------------------------------------------------------
// 1-pass tf32 GEMM, cp.async 3-stage pipeline + fused top-8 epilogue.
// CTA = 64 tokens x 64 experts, 8 warps (mw=wid&1: 32 tok, nw=wid>>1: 16 exp).
// ---------------------------------------------------------------------------
__global__ __launch_bounds__(256, 2) void gate_cp(
    const float* __restrict__ x, const float* __restrict__ W,
    float* __restrict__ out, int Ntok)
{
    extern __shared__ float sm[];
    const uint32_t sb = s2u(sm);
    __shared__ int scnt[NEXP];

    const int t    = threadIdx.x;
    const int wid  = t >> 5;
    const int lane = t & 31;
    const int gid  = lane >> 2;
    const int tig  = lane & 3;
    const int mw   = wid & 1;
    const int nw   = wid >> 1;
    const int tok0 = blockIdx.x * TILE_M;

    if (t < NEXP) scnt[t] = 0;

    float d[2][2][4];
#pragma unroll
    for (int i = 0; i < 2; i++)
#pragma unroll
        for (int j = 0; j < 2; j++)
#pragma unroll
            for (int k = 0; k < 4; k++) d[i][j][k] = 0.f;

    const float* xb = x + (size_t)tok0 * H;

    // row/seg mapping for this thread's 4 A- and 4 B- cp.async ops per stage
    // f = t + 256*i : row = f>>4 (0..63), seg = f&15 (16B units across KC=64)
#define ISSUE_STAGE(cc, st)                                                     \
    do {                                                                        \
        uint32_t ab = sb + (uint32_t)(st) * STG_W * 4;                          \
        uint32_t bb = ab + A_BUF_W * 4;                                         \
        const float* xs = xb + (size_t)(cc) * KC;                               \
        const float* ws = W + (size_t)(cc) * KC;                                \
        _Pragma("unroll")                                                       \
        for (int i = 0; i < 4; i++) {                                           \
            int f = t + 256 * i;                                                \
            int row = f >> 4, seg = f & 15;                                     \
            CP_ASYNC(ab + (uint32_t)(row * SA + seg * 4) * 4,                   \
                     xs + (size_t)row * H + seg * 4);                           \
            CP_ASYNC(bb + (uint32_t)(row * SA + seg * 4) * 4,                   \
                     ws + (size_t)row * H + seg * 4);                           \
        }                                                                       \
    } while (0)

    // prologue: stages 0, 1
    ISSUE_STAGE(0, 0); CP_COMMIT();
    ISSUE_STAGE(1, 1); CP_COMMIT();

    for (int c = 0; c < NCHUNK; c++) {
        // issue stage c+2 into buffer (c+2)%3 (freed by end-of-iter sync of c-1)
        if (c + 2 < NCHUNK) { ISSUE_STAGE(c + 2, (c + 2) % NST); }
        CP_COMMIT();
        CP_WAIT2();            // stage c's group complete
        __syncthreads();       // visible to all warps

        const int st = c % NST;
        const float* A = sm + st * STG_W;
        const float* B = A + A_BUF_W;

#pragma unroll
        for (int slab = 0; slab < 8; slab++) {
            const int k0 = slab * 8;
            uint32_t af[2][4], bf[2][2];
#pragma unroll
            for (int mt = 0; mt < 2; mt++) {
                int r = mw * 32 + mt * 16 + gid;
                af[mt][0] = __float_as_uint(A[(r    ) * SA + k0 + tig    ]);
                af[mt][1] = __float_as_uint(A[(r + 8) * SA + k0 + tig    ]);
                af[mt][2] = __float_as_uint(A[(r    ) * SA + k0 + tig + 4]);
                af[mt][3] = __float_as_uint(A[(r + 8) * SA + k0 + tig + 4]);
            }
#pragma unroll
            for (int nt = 0; nt < 2; nt++) {
                int e = nw * 16 + nt * 8 + gid;
                bf[nt][0] = __float_as_uint(B[e * SA + k0 + tig    ]);
                bf[nt][1] = __float_as_uint(B[e * SA + k0 + tig + 4]);
            }
#pragma unroll
            for (int mt = 0; mt < 2; mt++)
#pragma unroll
                for (int nt = 0; nt < 2; nt++)
                    mma_tf32(d[mt][nt], af[mt], bf[nt]);
        }
        __syncthreads();       // all warps done reading stage c before it is overwritten
    }

    // D fragments -> smem logits [64][65]
#pragma unroll
    for (int mt = 0; mt < 2; mt++)
#pragma unroll
        for (int nt = 0; nt < 2; nt++) {
            int r = mw * 32 + mt * 16 + gid;
            int cc = nw * 16 + nt * 8 + 2 * tig;
            sm[(r    ) * LOGIT_STRIDE + cc    ] = d[mt][nt][0];
            sm[(r    ) * LOGIT_STRIDE + cc + 1] = d[mt][nt][1];
            sm[(r + 8) * LOGIT_STRIDE + cc    ] = d[mt][nt][2];
            sm[(r + 8) * LOGIT_STRIDE + cc + 1] = d[mt][nt][3];
        }
    __syncthreads();

    if (t < TILE_M) {
        const float* row = sm + t * LOGIT_STRIDE;
        float sv[10]; int si[10];
        unsigned long long used = 0ull;
#pragma unroll 1
        for (int j = 0; j < 10; j++) {
            float best = -3.4e38f; int bi = 0;
#pragma unroll
            for (int e = 0; e < NEXP; e++) {
                float v = row[e];
                if (!((used >> e) & 1ull) && v > best) { best = v; bi = e; }
            }
            used |= 1ull << bi;
            sv[j] = best; si[j] = bi;
        }
        float ming = 3.4e38f;
#pragma unroll
        for (int j = 0; j < 9; j++) ming = fminf(ming, sv[j] - sv[j + 1]);

        const int g = tok0 + t;
        if (ming < GATE_THRESH) {
            int pos = atomicAdd(&g_fix_count, 1);
            g_fix_list[pos] = g;
        }
        float m = sv[0], ex[TOPK], ssum = 0.f;
#pragma unroll
        for (int j = 0; j < TOPK; j++) { ex[j] = expf(sv[j] - m); ssum += ex[j]; }
        float inv = 1.f / ssum;
        float* score_out = out + (size_t)g * TOPK;
        float* idx_out   = out + (size_t)Ntok * TOPK + (size_t)g * TOPK;
#pragma unroll
        for (int j = 0; j < TOPK; j++) {
            score_out[j] = ex[j] * inv;
            idx_out[j]   = (float)si[j];
            atomicAdd(&scnt[si[j]], 1);
        }
    }
    __syncthreads();
    if (t < NEXP && scnt[t]) atomicAdd(&g_icounts[t], scnt[t]);
}

// ---------------------------------------------------------------------------
// Tier-1 refine: plain fp32 recompute, 16 tokens/block (halved W L2 traffic),
// warp handles 2 tokens x 2 experts. Re-rank @1e-4; ambiguous -> tier-2.
// ---------------------------------------------------------------------------
__global__ __launch_bounds__(256, 2) void refine_kernel(
    const float* __restrict__ x, const float* __restrict__ W,
    float* __restrict__ out, int Ntok)
{
    __shared__ float Wc[NEXP * 133];
    __shared__ float xc[16 * 133];
    __shared__ float lgs[16][66];
    __shared__ int   toks[16];

    const int t    = threadIdx.x;
    const int wid  = t >> 5;
    const int lane = t & 31;
    const int nfix = g_fix_count;

    for (int base = blockIdx.x * 16; base < nfix; base += gridDim.x * 16) {
        const int nt = min(16, nfix - base);
        if (t < 16) toks[t] = g_fix_list[base + ((t < nt) ? t : 0)];
        __syncthreads();

        float a00 = 0.f, a01 = 0.f, a10 = 0.f, a11 = 0.f;
        for (int ch = 0; ch < 32; ch++) {
#pragma unroll
            for (int i = 0; i < 8; i++) {
                int f = t + 256 * i;              // 0..2047 f4
                int row = f >> 5, kq = f & 31;
                float4 v = *(const float4*)(W + (size_t)row * H + ch * 128 + kq * 4);
                float* dst = Wc + row * 133 + kq * 4;
                dst[0] = v.x; dst[1] = v.y; dst[2] = v.z; dst[3] = v.w;
            }
#pragma unroll
            for (int i = 0; i < 2; i++) {
                int f = t + 256 * i;              // 0..511 f4
                int row = f >> 5, kq = f & 31;
                float4 v = *(const float4*)(x + (size_t)toks[row] * H + ch * 128 + kq * 4);
                float* dst = xc + row * 133 + kq * 4;
                dst[0] = v.x; dst[1] = v.y; dst[2] = v.z; dst[3] = v.w;
            }
            __syncthreads();

            const float* x0 = xc + wid * 133;
            const float* x1 = xc + (wid + 8) * 133;
            const float* w0 = Wc + lane * 133;
            const float* w1 = Wc + (lane + 32) * 133;
#pragma unroll 16
            for (int k = 0; k < 128; k++) {
                float wv0 = w0[k], wv1 = w1[k];
                float xv0 = x0[k], xv1 = x1[k];
                a00 = fmaf(wv0, xv0, a00);
                a01 = fmaf(wv1, xv0, a01);
                a10 = fmaf(wv0, xv1, a10);
                a11 = fmaf(wv1, xv1, a11);
            }
            __syncthreads();
        }
        lgs[wid][lane]           = a00;
        lgs[wid][lane + 32]      = a01;
        lgs[wid + 8][lane]       = a10;
        lgs[wid + 8][lane + 32]  = a11;
        __syncthreads();

        if (t < nt) {
            const int tok = toks[t];
            const float* row = lgs[t];
            float sv[10]; int si[10];
            unsigned long long used = 0ull;
#pragma unroll 1
            for (int j = 0; j < 10; j++) {
                float best = -3.4e38f; int bi = 0;
#pragma unroll
                for (int e = 0; e < NEXP; e++) {
                    float v = row[e];
                    if (!((used >> e) & 1ull) && v > best) { best = v; bi = e; }
                }
                used |= 1ull << bi;
                sv[j] = best; si[j] = bi;
            }
            float ming = 3.4e38f;
#pragma unroll
            for (int j = 0; j < 9; j++) ming = fminf(ming, sv[j] - sv[j + 1]);

            if (ming < REFINE_THRESH) {
                int pos = atomicAdd(&g_fix2_count, 1);
                g_fix2_list[pos] = tok;
            } else {
                float* score_out = out + (size_t)tok * TOPK;
                float* idx_out   = out + (size_t)Ntok * TOPK + (size_t)tok * TOPK;
                float m = sv[0], ex[TOPK], ssum = 0.f;
#pragma unroll
                for (int j = 0; j < TOPK; j++) { ex[j] = expf(sv[j] - m); ssum += ex[j]; }
                float inv = 1.f / ssum;
#pragma unroll
                for (int j = 0; j < TOPK; j++) {
                    int olde = (int)idx_out[j];
                    score_out[j] = ex[j] * inv;
                    idx_out[j]   = (float)si[j];
                    if (si[j] != olde) {
                        atomicAdd(&g_icounts[si[j]], 1);
                        atomicSub(&g_icounts[olde], 1);
                    }
                }
            }
        }
        __syncthreads();
    }
}

// ---------------------------------------------------------------------------
// Tier-2 exact: compensated recompute (coalesced), 1 token/block.
// ---------------------------------------------------------------------------
__global__ __launch_bounds__(256, 2) void exact_kernel(
    const float* __restrict__ x, const float* __restrict__ W,
    float* __restrict__ out, int Ntok)
{
    __shared__ float  Wc[NEXP * 133];
    __shared__ float  xcc[132];
    __shared__ double lg[NEXP];

    const int t   = threadIdx.x;
    const int e   = t >> 2;
    const int sub = t & 3;
    const int nfix2 = g_fix2_count;

    for (int fi = blockIdx.x; fi < nfix2; fi += gridDim.x) {
        const int tok = g_fix2_list[fi];
        float s = 0.f, c = 0.f;

        for (int ch = 0; ch < 32; ch++) {
#pragma unroll
            for (int i = 0; i < 8; i++) {
                int f = t + 256 * i;
                int row = f >> 5, kq = f & 31;
                float4 v = *(const float4*)(W + (size_t)row * H + ch * 128 + kq * 4);
                float* dst = Wc + row * 133 + kq * 4;
                dst[0] = v.x; dst[1] = v.y; dst[2] = v.z; dst[3] = v.w;
            }
            if (t < 32) {
                float4 v = *(const float4*)(x + (size_t)tok * H + ch * 128 + t * 4);
                xcc[t * 4 + 0] = v.x; xcc[t * 4 + 1] = v.y;
                xcc[t * 4 + 2] = v.z; xcc[t * 4 + 3] = v.w;
            }
            __syncthreads();

            const float* wr = Wc + e * 133;
#pragma unroll 8
            for (int j = 0; j < 32; j++) {
                int k = sub + 4 * j;
                float xv = xcc[k], wv = wr[k];
                float p  = xv * wv;
                float pe = fmaf(xv, wv, -p);
                float tt = s + p;
                c += (fabsf(s) >= fabsf(p)) ? ((s - tt) + p) : ((p - tt) + s);
                s  = tt;
                c += pe;
            }
            __syncthreads();
        }
        double dd = (double)s + (double)c;
        dd += __shfl_down_sync(0xffffffffu, dd, 1);
        dd += __shfl_down_sync(0xffffffffu, dd, 2);
        if (sub == 0) lg[e] = dd;
        __syncthreads();

        if (t == 0) {
            float* score_out = out + (size_t)tok * TOPK;
            float* idx_out   = out + (size_t)Ntok * TOPK + (size_t)tok * TOPK;
            int olde[TOPK];
#pragma unroll
            for (int j = 0; j < TOPK; j++) olde[j] = (int)idx_out[j];

            double sv[TOPK]; int si[TOPK];
#pragma unroll 1
            for (int j = 0; j < TOPK; j++) {
                double best = -1e300; int bi = 0;
                for (int ee = 0; ee < NEXP; ee++) {
                    double v = lg[ee];
                    if (v > best) { best = v; bi = ee; }
                }
                sv[j] = best; si[j] = bi;
                lg[bi] = -1e300;
            }
            float m = (float)sv[0], ex[TOPK], ssum = 0.f;
#pragma unroll
            for (int j = 0; j < TOPK; j++) { ex[j] = expf((float)sv[j] - m); ssum += ex[j]; }
            float inv = 1.f / ssum;
#pragma unroll
            for (int j = 0; j < TOPK; j++) {
                score_out[j] = ex[j] * inv;
                idx_out[j]   = (float)si[j];
                if (si[j] != olde[j]) {
                    atomicAdd(&g_icounts[si[j]], 1);
                    atomicSub(&g_icounts[olde[j]], 1);
                }
            }
        }
        __syncthreads();
    }
}

// ---------------------------------------------------------------------------
// loss; resets all replay state.
// ---------------------------------------------------------------------------
__global__ void loss_kernel(float* __restrict__ out, int Ntok)
{
    const int t = threadIdx.x;   // 64
    float dd = (float)g_icounts[t] / (float)Ntok - (1.0f / 64.0f);
    float v = dd * dd;
#pragma unroll
    for (int off = 16; off > 0; off >>= 1)
        v += __shfl_down_sync(0xffffffffu, v, off);
    __shared__ float red[2];
    if ((t & 31) == 0) red[t >> 5] = v;
    __syncthreads();
    g_icounts[t] = 0;
    if (t == 0) {
        out[0] = 0.01f * (red[0] + red[1]);
        g_fix_count  = 0;
        g_fix2_count = 0;
    }
}

extern "C" void kernel_launch(void* const* d_in, const int* in_sizes, int n_in,
                              void* d_out, int out_size)
{
    const float* x = (const float*)d_in[0];
    const float* W = (const float*)d_in[1];
    float* out = (float*)d_out;

    int Ntok  = in_sizes[0] / H;     // 16384
    int n_sel = Ntok * TOPK;         // 131072

    cudaFuncSetAttribute(gate_cp, cudaFuncAttributeMaxDynamicSharedMemorySize, SMEM_BYTES);

    gate_cp<<<Ntok / TILE_M, 256, SMEM_BYTES>>>(x, W, out, Ntok);
    refine_kernel<<<296, 256>>>(x, W, out, Ntok);
    exact_kernel<<<256, 256>>>(x, W, out, Ntok);
    loss_kernel<<<1, 64>>>(out + (size_t)2 * n_sel, Ntok);
}

// round 17
// speedup vs baseline: 12.8385x; 1.0327x over previous
#include <cuda_runtime.h>
#include <math.h>
#include <stdint.h>

#define H 4096
#define NEXP 64
#define TOPK 8
#define TILE_M 64
#define KC 64
#define NCHUNK (H / KC)          // 64
#define NST 3
#define SA 68                    // smem row stride words (68%32==4 -> conflict-free frags)

#define A_BUF_W (TILE_M * SA)               // 4352 words
#define B_BUF_W (NEXP * SA)                 // 4352 words
#define STG_W   (A_BUF_W + B_BUF_W)         // 8704 words
#define SMEM_BYTES (NST * STG_W * 4)        // 104448 B
#define LOGIT_STRIDE 65
#define GATE_THRESH 3e-3f
#define REFINE_THRESH 1e-4f

// device scratch (alloc-free rule)
__device__ int g_icounts[NEXP];
__device__ int g_fix_count;
__device__ int g_fix_list[16384];
__device__ int g_fix2_count;
__device__ int g_fix2_list[16384];

static __device__ __forceinline__ uint32_t s2u(const void* p) {
    uint32_t a;
    asm("{ .reg .u64 t; cvta.to.shared.u64 t, %1; cvt.u32.u64 %0, t; }" : "=r"(a) : "l"(p));
    return a;
}
#define CP_ASYNC(dst, src) \
    asm volatile("cp.async.cg.shared.global [%0], [%1], 16;" :: "r"(dst), "l"(src))
#define CP_COMMIT() asm volatile("cp.async.commit_group;" ::: "memory")
#define CP_WAIT1()  asm volatile("cp.async.wait_group 1;" ::: "memory")

static __device__ __forceinline__ void mma_tf32(float* d, const uint32_t* a, const uint32_t* b) {
    asm volatile(
        "mma.sync.aligned.m16n8k8.row.col.f32.tf32.tf32.f32 "
        "{%0,%1,%2,%3}, {%4,%5,%6,%7}, {%8,%9}, {%0,%1,%2,%3};"
        : "+f"(d[0]), "+f"(d[1]), "+f"(d[2]), "+f"(d[3])
        : "r"(a[0]), "r"(a[1]), "r"(a[2]), "r"(a[3]), "r"(b[0]), "r"(b[1]));
}

// ---------------------------------------------------------------------------
// 1-pass tf32 GEMM, cp.async 3-stage pipeline, ONE barrier per chunk.
// CTA = 64 tokens x 64 experts; 8 warps = 2(tok) x 2(exp) x 2(k-half),
// each warp a 32x32 tile over half the chunk K. k-halves summed via smem.
// ---------------------------------------------------------------------------
__global__ __launch_bounds__(256, 2) void gate_cp(
    const float* __restrict__ x, const float* __restrict__ W,
    float* __restrict__ out, int Ntok)
{
    extern __shared__ float sm[];
    const uint32_t sb = s2u(sm);
    __shared__ int scnt[NEXP];

    const int t    = threadIdx.x;
    const int wid  = t >> 5;
    const int lane = t & 31;
    const int gid  = lane >> 2;
    const int tig  = lane & 3;
    const int mw   = wid & 1;          // token half (32 tokens)
    const int nw   = (wid >> 1) & 1;   // expert half (32 experts)
    const int kw   = wid >> 2;         // k half of each chunk
    const int tok0 = blockIdx.x * TILE_M;

    if (t < NEXP) scnt[t] = 0;

    float d[2][4][4];
#pragma unroll
    for (int i = 0; i < 2; i++)
#pragma unroll
        for (int j = 0; j < 4; j++)
#pragma unroll
            for (int k = 0; k < 4; k++) d[i][j][k] = 0.f;

    const float* xb = x + (size_t)tok0 * H;

#define ISSUE_STAGE(cc, st)                                                     \
    do {                                                                        \
        uint32_t ab = sb + (uint32_t)(st) * STG_W * 4;                          \
        uint32_t bb = ab + A_BUF_W * 4;                                         \
        const float* xs = xb + (size_t)(cc) * KC;                               \
        const float* ws = W + (size_t)(cc) * KC;                                \
        _Pragma("unroll")                                                       \
        for (int i = 0; i < 4; i++) {                                           \
            int f = t + 256 * i;                                                \
            int row = f >> 4, seg = f & 15;                                     \
            CP_ASYNC(ab + (uint32_t)(row * SA + seg * 4) * 4,                   \
                     xs + (size_t)row * H + seg * 4);                           \
            CP_ASYNC(bb + (uint32_t)(row * SA + seg * 4) * 4,                   \
                     ws + (size_t)row * H + seg * 4);                           \
        }                                                                       \
    } while (0)

    ISSUE_STAGE(0, 0); CP_COMMIT();
    ISSUE_STAGE(1, 1); CP_COMMIT();

    for (int c = 0; c < NCHUNK; c++) {
        CP_WAIT1();            // my groups for stage c retired
        __syncthreads();       // publish stage c; also proves mma(c-1) done by all

        // prefetch stage c+2 into buffer (c+2)%3 == (c-1)%3 (safe after sync)
        if (c + 2 < NCHUNK) { ISSUE_STAGE(c + 2, (c + 2) % NST); }
        CP_COMMIT();

        const int st = c % NST;
        const float* A = sm + st * STG_W;
        const float* B = A + A_BUF_W;

#pragma unroll
        for (int slab = 0; slab < 4; slab++) {
            const int k0 = (kw * 4 + slab) * 8;
            uint32_t af[2][4], bf[4][2];
#pragma unroll
            for (int mt = 0; mt < 2; mt++) {
                int r = mw * 32 + mt * 16 + gid;
                af[mt][0] = __float_as_uint(A[(r    ) * SA + k0 + tig    ]);
                af[mt][1] = __float_as_uint(A[(r + 8) * SA + k0 + tig    ]);
                af[mt][2] = __float_as_uint(A[(r    ) * SA + k0 + tig + 4]);
                af[mt][3] = __float_as_uint(A[(r + 8) * SA + k0 + tig + 4]);
            }
#pragma unroll
            for (int nt = 0; nt < 4; nt++) {
                int e = nw * 32 + nt * 8 + gid;
                bf[nt][0] = __float_as_uint(B[e * SA + k0 + tig    ]);
                bf[nt][1] = __float_as_uint(B[e * SA + k0 + tig + 4]);
            }
#pragma unroll
            for (int mt = 0; mt < 2; mt++)
#pragma unroll
                for (int nt = 0; nt < 4; nt++)
                    mma_tf32(d[mt][nt], af[mt], bf[nt]);
        }
    }
    __syncthreads();   // last stage fully consumed before smem reuse as logits

    // ---- k-half reduction into smem logits [64][65] ----
    if (kw == 0) {
#pragma unroll
        for (int mt = 0; mt < 2; mt++)
#pragma unroll
            for (int nt = 0; nt < 4; nt++) {
                int r = mw * 32 + mt * 16 + gid;
                int cc = nw * 32 + nt * 8 + 2 * tig;
                sm[(r    ) * LOGIT_STRIDE + cc    ] = d[mt][nt][0];
                sm[(r    ) * LOGIT_STRIDE + cc + 1] = d[mt][nt][1];
                sm[(r + 8) * LOGIT_STRIDE + cc    ] = d[mt][nt][2];
                sm[(r + 8) * LOGIT_STRIDE + cc + 1] = d[mt][nt][3];
            }
    }
    __syncthreads();
    if (kw == 1) {
#pragma unroll
        for (int mt = 0; mt < 2; mt++)
#pragma unroll
            for (int nt = 0; nt < 4; nt++) {
                int r = mw * 32 + mt * 16 + gid;
                int cc = nw * 32 + nt * 8 + 2 * tig;
                sm[(r    ) * LOGIT_STRIDE + cc    ] += d[mt][nt][0];
                sm[(r    ) * LOGIT_STRIDE + cc + 1] += d[mt][nt][1];
                sm[(r + 8) * LOGIT_STRIDE + cc    ] += d[mt][nt][2];
                sm[(r + 8) * LOGIT_STRIDE + cc + 1] += d[mt][nt][3];
            }
    }
    __syncthreads();

    // ---- epilogue: top-10 scan + softmax + gap flag + counting ----
    if (t < TILE_M) {
        const float* row = sm + t * LOGIT_STRIDE;
        float sv[10]; int si[10];
        unsigned long long used = 0ull;
#pragma unroll 1
        for (int j = 0; j < 10; j++) {
            float best = -3.4e38f; int bi = 0;
#pragma unroll
            for (int e = 0; e < NEXP; e++) {
                float v = row[e];
                if (!((used >> e) & 1ull) && v > best) { best = v; bi = e; }
            }
            used |= 1ull << bi;
            sv[j] = best; si[j] = bi;
        }
        float ming = 3.4e38f;
#pragma unroll
        for (int j = 0; j < 9; j++) ming = fminf(ming, sv[j] - sv[j + 1]);

        const int g = tok0 + t;
        if (ming < GATE_THRESH) {
            int pos = atomicAdd(&g_fix_count, 1);
            g_fix_list[pos] = g;
        }
        float m = sv[0], ex[TOPK], ssum = 0.f;
#pragma unroll
        for (int j = 0; j < TOPK; j++) { ex[j] = expf(sv[j] - m); ssum += ex[j]; }
        float inv = 1.f / ssum;
        float* score_out = out + (size_t)g * TOPK;
        float* idx_out   = out + (size_t)Ntok * TOPK + (size_t)g * TOPK;
#pragma unroll
        for (int j = 0; j < TOPK; j++) {
            score_out[j] = ex[j] * inv;
            idx_out[j]   = (float)si[j];
            atomicAdd(&scnt[si[j]], 1);
        }
    }
    __syncthreads();
    if (t < NEXP && scnt[t]) atomicAdd(&g_icounts[t], scnt[t]);
}

// ---------------------------------------------------------------------------
// Tier-1 refine: plain fp32 recompute, 16 tokens/block, warp = 2 tok x 2 exp.
// Re-rank @1e-4; ambiguous -> tier-2; else overwrite + patch counts.
// ---------------------------------------------------------------------------
__global__ __launch_bounds__(256, 2) void refine_kernel(
    const float* __restrict__ x, const float* __restrict__ W,
    float* __restrict__ out, int Ntok)
{
    __shared__ float Wc[NEXP * 133];
    __shared__ float xc[16 * 133];
    __shared__ float lgs[16][66];
    __shared__ int   toks[16];

    const int t    = threadIdx.x;
    const int wid  = t >> 5;
    const int lane = t & 31;
    const int nfix = g_fix_count;

    for (int base = blockIdx.x * 16; base < nfix; base += gridDim.x * 16) {
        const int nt = min(16, nfix - base);
        if (t < 16) toks[t] = g_fix_list[base + ((t < nt) ? t : 0)];
        __syncthreads();

        float a00 = 0.f, a01 = 0.f, a10 = 0.f, a11 = 0.f;
        for (int ch = 0; ch < 32; ch++) {
#pragma unroll
            for (int i = 0; i < 8; i++) {
                int f = t + 256 * i;
                int row = f >> 5, kq = f & 31;
                float4 v = *(const float4*)(W + (size_t)row * H + ch * 128 + kq * 4);
                float* dst = Wc + row * 133 + kq * 4;
                dst[0] = v.x; dst[1] = v.y; dst[2] = v.z; dst[3] = v.w;
            }
#pragma unroll
            for (int i = 0; i < 2; i++) {
                int f = t + 256 * i;
                int row = f >> 5, kq = f & 31;
                float4 v = *(const float4*)(x + (size_t)toks[row] * H + ch * 128 + kq * 4);
                float* dst = xc + row * 133 + kq * 4;
                dst[0] = v.x; dst[1] = v.y; dst[2] = v.z; dst[3] = v.w;
            }
            __syncthreads();

            const float* x0 = xc + wid * 133;
            const float* x1 = xc + (wid + 8) * 133;
            const float* w0 = Wc + lane * 133;
            const float* w1 = Wc + (lane + 32) * 133;
#pragma unroll 16
            for (int k = 0; k < 128; k++) {
                float wv0 = w0[k], wv1 = w1[k];
                float xv0 = x0[k], xv1 = x1[k];
                a00 = fmaf(wv0, xv0, a00);
                a01 = fmaf(wv1, xv0, a01);
                a10 = fmaf(wv0, xv1, a10);
                a11 = fmaf(wv1, xv1, a11);
            }
            __syncthreads();
        }
        lgs[wid][lane]           = a00;
        lgs[wid][lane + 32]      = a01;
        lgs[wid + 8][lane]       = a10;
        lgs[wid + 8][lane + 32]  = a11;
        __syncthreads();

        if (t < nt) {
            const int tok = toks[t];
            const float* row = lgs[t];
            float sv[10]; int si[10];
            unsigned long long used = 0ull;
#pragma unroll 1
            for (int j = 0; j < 10; j++) {
                float best = -3.4e38f; int bi = 0;
#pragma unroll
                for (int e = 0; e < NEXP; e++) {
                    float v = row[e];
                    if (!((used >> e) & 1ull) && v > best) { best = v; bi = e; }
                }
                used |= 1ull << bi;
                sv[j] = best; si[j] = bi;
            }
            float ming = 3.4e38f;
#pragma unroll
            for (int j = 0; j < 9; j++) ming = fminf(ming, sv[j] - sv[j + 1]);

            if (ming < REFINE_THRESH) {
                int pos = atomicAdd(&g_fix2_count, 1);
                g_fix2_list[pos] = tok;
            } else {
                float* score_out = out + (size_t)tok * TOPK;
                float* idx_out   = out + (size_t)Ntok * TOPK + (size_t)tok * TOPK;
                float m = sv[0], ex[TOPK], ssum = 0.f;
#pragma unroll
                for (int j = 0; j < TOPK; j++) { ex[j] = expf(sv[j] - m); ssum += ex[j]; }
                float inv = 1.f / ssum;
#pragma unroll
                for (int j = 0; j < TOPK; j++) {
                    int olde = (int)idx_out[j];
                    score_out[j] = ex[j] * inv;
                    idx_out[j]   = (float)si[j];
                    if (si[j] != olde) {
                        atomicAdd(&g_icounts[si[j]], 1);
                        atomicSub(&g_icounts[olde], 1);
                    }
                }
            }
        }
        __syncthreads();
    }
}

// ---------------------------------------------------------------------------
// Tier-2 exact: compensated recompute (coalesced), 1 token/block.
// ---------------------------------------------------------------------------
__global__ __launch_bounds__(256, 2) void exact_kernel(
    const float* __restrict__ x, const float* __restrict__ W,
    float* __restrict__ out, int Ntok)
{
    __shared__ float  Wc[NEXP * 133];
    __shared__ float  xcc[132];
    __shared__ double lg[NEXP];

    const int t   = threadIdx.x;
    const int e   = t >> 2;
    const int sub = t & 3;
    const int nfix2 = g_fix2_count;

    for (int fi = blockIdx.x; fi < nfix2; fi += gridDim.x) {
        const int tok = g_fix2_list[fi];
        float s = 0.f, c = 0.f;

        for (int ch = 0; ch < 32; ch++) {
#pragma unroll
            for (int i = 0; i < 8; i++) {
                int f = t + 256 * i;
                int row = f >> 5, kq = f & 31;
                float4 v = *(const float4*)(W + (size_t)row * H + ch * 128 + kq * 4);
                float* dst = Wc + row * 133 + kq * 4;
                dst[0] = v.x; dst[1] = v.y; dst[2] = v.z; dst[3] = v.w;
            }
            if (t < 32) {
                float4 v = *(const float4*)(x + (size_t)tok * H + ch * 128 + t * 4);
                xcc[t * 4 + 0] = v.x; xcc[t * 4 + 1] = v.y;
                xcc[t * 4 + 2] = v.z; xcc[t * 4 + 3] = v.w;
            }
            __syncthreads();

            const float* wr = Wc + e * 133;
#pragma unroll 8
            for (int j = 0; j < 32; j++) {
                int k = sub + 4 * j;
                float xv = xcc[k], wv = wr[k];
                float p  = xv * wv;
                float pe = fmaf(xv, wv, -p);
                float tt = s + p;
                c += (fabsf(s) >= fabsf(p)) ? ((s - tt) + p) : ((p - tt) + s);
                s  = tt;
                c += pe;
            }
            __syncthreads();
        }
        double dd = (double)s + (double)c;
        dd += __shfl_down_sync(0xffffffffu, dd, 1);
        dd += __shfl_down_sync(0xffffffffu, dd, 2);
        if (sub == 0) lg[e] = dd;
        __syncthreads();

        if (t == 0) {
            float* score_out = out + (size_t)tok * TOPK;
            float* idx_out   = out + (size_t)Ntok * TOPK + (size_t)tok * TOPK;
            int olde[TOPK];
#pragma unroll
            for (int j = 0; j < TOPK; j++) olde[j] = (int)idx_out[j];

            double sv[TOPK]; int si[TOPK];
#pragma unroll 1
            for (int j = 0; j < TOPK; j++) {
                double best = -1e300; int bi = 0;
                for (int ee = 0; ee < NEXP; ee++) {
                    double v = lg[ee];
                    if (v > best) { best = v; bi = ee; }
                }
                sv[j] = best; si[j] = bi;
                lg[bi] = -1e300;
            }
            float m = (float)sv[0], ex[TOPK], ssum = 0.f;
#pragma unroll
            for (int j = 0; j < TOPK; j++) { ex[j] = expf((float)sv[j] - m); ssum += ex[j]; }
            float inv = 1.f / ssum;
#pragma unroll
            for (int j = 0; j < TOPK; j++) {
                score_out[j] = ex[j] * inv;
                idx_out[j]   = (float)si[j];
                if (si[j] != olde[j]) {
                    atomicAdd(&g_icounts[si[j]], 1);
                    atomicSub(&g_icounts[olde[j]], 1);
                }
            }
        }
        __syncthreads();
    }
}

// ---------------------------------------------------------------------------
// loss; resets all replay state.
// ---------------------------------------------------------------------------
__global__ void loss_kernel(float* __restrict__ out, int Ntok)
{
    const int t = threadIdx.x;   // 64
    float dd = (float)g_icounts[t] / (float)Ntok - (1.0f / 64.0f);
    float v = dd * dd;
#pragma unroll
    for (int off = 16; off > 0; off >>= 1)
        v += __shfl_down_sync(0xffffffffu, v, off);
    __shared__ float red[2];
    if ((t & 31) == 0) red[t >> 5] = v;
    __syncthreads();
    g_icounts[t] = 0;
    if (t == 0) {
        out[0] = 0.01f * (red[0] + red[1]);
        g_fix_count  = 0;
        g_fix2_count = 0;
    }
}

extern "C" void kernel_launch(void* const* d_in, const int* in_sizes, int n_in,
                              void* d_out, int out_size)
{
    const float* x = (const float*)d_in[0];
    const float* W = (const float*)d_in[1];
    float* out = (float*)d_out;

    int Ntok  = in_sizes[0] / H;     // 16384
    int n_sel = Ntok * TOPK;         // 131072

    cudaFuncSetAttribute(gate_cp, cudaFuncAttributeMaxDynamicSharedMemorySize, SMEM_BYTES);

    gate_cp<<<Ntok / TILE_M, 256, SMEM_BYTES>>>(x, W, out, Ntok);
    refine_kernel<<<296, 256>>>(x, W, out, Ntok);
    exact_kernel<<<256, 256>>>(x, W, out, Ntok);
    loss_kernel<<<1, 64>>>(out + (size_t)2 * n_sel, Ntok);
}